// round 1
// baseline (speedup 1.0000x reference)
#include <cuda_runtime.h>
#include <math.h>

// ---------------- problem constants ----------------
#define BB     2
#define CC     512
#define NQ     2304      // 48*48 tokens
#define INNER_ 512
#define HEADS_ 8
#define DHEAD_ 64
#define CTX    77
#define CTXD   768
#define FFI    2048
#define MTOK   (BB*NQ)   // 4608

// ---------------- scratch (device globals; no allocation allowed) ---------
__device__ float g_hn[MTOK*INNER_];
__device__ float g_t [MTOK*INNER_];
__device__ float g_q [MTOK*INNER_];
__device__ float g_k [MTOK*INNER_];
__device__ float g_v [MTOK*INNER_];
__device__ float g_at[MTOK*INNER_];
__device__ float g_y [MTOK*INNER_];
__device__ float g_kc[BB*CTX*INNER_];
__device__ float g_vc[BB*CTX*INNER_];
__device__ float g_ff[MTOK*4096];
__device__ float g_gl[MTOK*FFI];
__device__ float g_stat[BB*32*2];

// ---------------- GroupNorm stats: one block per (b, group) ----------------
__global__ void gn_stats_k(const float* __restrict__ x, float* __restrict__ st)
{
    int bg = blockIdx.x;            // b*32 + g
    int b  = bg >> 5, g = bg & 31;
    const float* base = x + ((size_t)b*CC + (size_t)g*16) * NQ;   // 16 contiguous channels
    float s = 0.f, s2 = 0.f;
    for (int i = threadIdx.x; i < 16*NQ; i += 256) {
        float v = base[i];
        s += v; s2 += v*v;
    }
    // block reduce (8 warps)
    for (int o = 16; o > 0; o >>= 1) {
        s  += __shfl_down_sync(~0u, s,  o);
        s2 += __shfl_down_sync(~0u, s2, o);
    }
    __shared__ float sh1[8], sh2[8];
    int w = threadIdx.x >> 5, lane = threadIdx.x & 31;
    if (lane == 0) { sh1[w] = s; sh2[w] = s2; }
    __syncthreads();
    if (threadIdx.x == 0) {
        float S = 0.f, S2 = 0.f;
        for (int i = 0; i < 8; i++) { S += sh1[i]; S2 += sh2[i]; }
        float mean = S / (16.f*NQ);
        float var  = S2 / (16.f*NQ) - mean*mean;
        st[bg*2]   = mean;
        st[bg*2+1] = rsqrtf(var + 1e-6f);
    }
}

// --------- GroupNorm apply + NCHW -> [b,n,c] transpose (tiled) -------------
__global__ void gn_apply_t_k(const float* __restrict__ x, const float* __restrict__ st,
                             const float* __restrict__ gg, const float* __restrict__ gb,
                             float* __restrict__ o)
{
    __shared__ float tile[32][33];
    int n0 = blockIdx.x * 32, c0 = blockIdx.y * 32, b = blockIdx.z;
    int tx = threadIdx.x, ty = threadIdx.y;
    #pragma unroll
    for (int i = 0; i < 4; i++) {
        int c = c0 + ty + i*8;
        int g = c >> 4;
        float mean = st[(b*32+g)*2], rstd = st[(b*32+g)*2+1];
        float v = x[((size_t)b*CC + c)*NQ + n0 + tx];
        tile[ty + i*8][tx] = (v - mean) * rstd * gg[c] + gb[c];
    }
    __syncthreads();
    #pragma unroll
    for (int i = 0; i < 4; i++) {
        int n = n0 + ty + i*8;
        o[((size_t)b*NQ + n)*INNER_ + c0 + tx] = tile[tx][ty + i*8];
    }
}

// --------- final: [b,n,c] -> NCHW transpose + bias-free residual add -------
__global__ void out_add_k(const float* __restrict__ yb, const float* __restrict__ x,
                          float* __restrict__ o)
{
    __shared__ float tile[32][33];
    int n0 = blockIdx.x * 32, c0 = blockIdx.y * 32, b = blockIdx.z;
    int tx = threadIdx.x, ty = threadIdx.y;
    #pragma unroll
    for (int i = 0; i < 4; i++) {
        int n = n0 + ty + i*8;
        tile[ty + i*8][tx] = yb[((size_t)b*NQ + n)*INNER_ + c0 + tx];
    }
    __syncthreads();
    #pragma unroll
    for (int i = 0; i < 4; i++) {
        int c = c0 + ty + i*8;
        size_t idx = ((size_t)b*CC + c)*NQ + n0 + tx;
        o[idx] = tile[tx][ty + i*8] + x[idx];
    }
}

// ---------------- LayerNorm over 512: one block per row --------------------
__global__ void ln_k(const float* __restrict__ X, const float* __restrict__ g,
                     const float* __restrict__ bb, float* __restrict__ O)
{
    int row = blockIdx.x;
    int t = threadIdx.x;          // 128 threads, 4 floats each
    const float4 v = ((const float4*)(X + (size_t)row*INNER_))[t];
    float s  = v.x + v.y + v.z + v.w;
    float s2 = v.x*v.x + v.y*v.y + v.z*v.z + v.w*v.w;
    for (int o = 16; o > 0; o >>= 1) {
        s  += __shfl_down_sync(~0u, s,  o);
        s2 += __shfl_down_sync(~0u, s2, o);
    }
    __shared__ float sh1[4], sh2[4];
    int w = t >> 5, lane = t & 31;
    if (lane == 0) { sh1[w] = s; sh2[w] = s2; }
    __syncthreads();
    if (t == 0) {
        float S = sh1[0]+sh1[1]+sh1[2]+sh1[3];
        float S2 = sh2[0]+sh2[1]+sh2[2]+sh2[3];
        float mean = S / 512.f;
        float var  = S2 / 512.f - mean*mean;
        sh1[0] = mean;
        sh2[0] = rsqrtf(var + 1e-5f);
    }
    __syncthreads();
    float mean = sh1[0], rstd = sh2[0];
    float4 g4 = ((const float4*)g)[t];
    float4 b4 = ((const float4*)bb)[t];
    float4 o;
    o.x = (v.x-mean)*rstd*g4.x + b4.x;
    o.y = (v.y-mean)*rstd*g4.y + b4.y;
    o.z = (v.z-mean)*rstd*g4.z + b4.z;
    o.w = (v.w-mean)*rstd*g4.w + b4.w;
    ((float4*)(O + (size_t)row*INNER_))[t] = o;
}

// ---------------- generic SGEMM: C = A[M,K] @ W[K,N] (+bias)(+res) ---------
// BM=BN=128, BK=16, 256 threads, 8x8 micro-tile. N%128==0, K%16==0; M guarded.
__global__ void __launch_bounds__(256) sgemm_k(
    const float* __restrict__ A, const float* __restrict__ W,
    const float* __restrict__ bias, const float* __restrict__ res,
    float* __restrict__ C, int M, int N, int K)
{
    __shared__ float As[16][128];
    __shared__ float Bs[16][128];
    const int t  = threadIdx.x;
    const int bn = blockIdx.x * 128;
    const int bm = blockIdx.y * 128;
    const int ty = t >> 4, tx = t & 15;

    float acc[8][8];
    #pragma unroll
    for (int i = 0; i < 8; i++)
        #pragma unroll
        for (int j = 0; j < 8; j++) acc[i][j] = 0.f;

    const int a_m = t >> 2;          // 0..63
    const int a_k = (t & 3) * 4;     // 0,4,8,12
    const int b_k = t >> 5;          // 0..7
    const int b_n = (t & 31) * 4;    // 0..124

    for (int k0 = 0; k0 < K; k0 += 16) {
        #pragma unroll
        for (int jj = 0; jj < 2; jj++) {
            int m = a_m + jj*64;
            float4 v = make_float4(0.f,0.f,0.f,0.f);
            if (bm + m < M)
                v = *(const float4*)&A[(size_t)(bm+m)*K + k0 + a_k];
            As[a_k+0][m] = v.x; As[a_k+1][m] = v.y;
            As[a_k+2][m] = v.z; As[a_k+3][m] = v.w;
        }
        #pragma unroll
        for (int jj = 0; jj < 2; jj++) {
            int k = b_k + jj*8;
            *(float4*)&Bs[k][b_n] = *(const float4*)&W[(size_t)(k0+k)*N + bn + b_n];
        }
        __syncthreads();
        #pragma unroll
        for (int kk = 0; kk < 16; kk++) {
            float4 a0 = *(float4*)&As[kk][ty*4];
            float4 a1 = *(float4*)&As[kk][ty*4 + 64];
            float4 b0 = *(float4*)&Bs[kk][tx*4];
            float4 b1 = *(float4*)&Bs[kk][tx*4 + 64];
            float ar[8] = {a0.x,a0.y,a0.z,a0.w,a1.x,a1.y,a1.z,a1.w};
            float br[8] = {b0.x,b0.y,b0.z,b0.w,b1.x,b1.y,b1.z,b1.w};
            #pragma unroll
            for (int i = 0; i < 8; i++)
                #pragma unroll
                for (int j = 0; j < 8; j++)
                    acc[i][j] += ar[i]*br[j];
        }
        __syncthreads();
    }

    #pragma unroll
    for (int ii = 0; ii < 2; ii++) {
        #pragma unroll
        for (int i = 0; i < 4; i++) {
            int m = bm + ii*64 + ty*4 + i;
            if (m >= M) continue;
            #pragma unroll
            for (int jj = 0; jj < 2; jj++) {
                int n = bn + jj*64 + tx*4;
                float4 o;
                o.x = acc[ii*4+i][jj*4+0];
                o.y = acc[ii*4+i][jj*4+1];
                o.z = acc[ii*4+i][jj*4+2];
                o.w = acc[ii*4+i][jj*4+3];
                if (bias) {
                    const float4 bi = *(const float4*)&bias[n];
                    o.x += bi.x; o.y += bi.y; o.z += bi.z; o.w += bi.w;
                }
                if (res) {
                    const float4 r4 = *(const float4*)&res[(size_t)m*N + n];
                    o.x += r4.x; o.y += r4.y; o.z += r4.z; o.w += r4.w;
                }
                *(float4*)&C[(size_t)m*N + n] = o;
            }
        }
    }
}

// ---------------- flash-style attention ------------------------------------
// grid: (n_q/64, HEADS, B). 64-query tile, 32-key tiles, online softmax.
// Q/K/V are [b*nrows, 512] with the head at column h*64. SCALE = 0.125.
__global__ void __launch_bounds__(256) attn_k(
    const float* __restrict__ Q, const float* __restrict__ Kb,
    const float* __restrict__ Vb, float* __restrict__ O,
    int n_q, int n_kv)
{
    __shared__ float Qs[64][68];
    __shared__ float Ks[32][68];
    __shared__ float Vs[32][68];
    __shared__ float Sx[64][33];
    __shared__ float mrow[64], lrow[64], arow[64];

    const int t  = threadIdx.x;
    const int h  = blockIdx.y, b = blockIdx.z;
    const int q0 = blockIdx.x * 64;
    const float* qb = Q  + ((size_t)b*n_q )*INNER_ + h*DHEAD_;
    const float* kb = Kb + ((size_t)b*n_kv)*INNER_ + h*DHEAD_;
    const float* vb = Vb + ((size_t)b*n_kv)*INNER_ + h*DHEAD_;

    // load Q tile: 64x64 = 1024 float4
    #pragma unroll
    for (int j = 0; j < 4; j++) {
        int idx4 = t + j*256;
        int r = idx4 >> 4, c4 = (idx4 & 15) * 4;
        float4 v = *(const float4*)&qb[(size_t)(q0 + r)*INNER_ + c4];
        Qs[r][c4+0] = v.x; Qs[r][c4+1] = v.y; Qs[r][c4+2] = v.z; Qs[r][c4+3] = v.w;
    }
    if (t < 64) { mrow[t] = -1e30f; lrow[t] = 0.f; }

    float acc[16];
    #pragma unroll
    for (int i = 0; i < 16; i++) acc[i] = 0.f;

    const int r  = t >> 2;     // query row this thread scores
    const int jq = t & 3;      // quad id (key / dim interleave)

    const int ntiles = (n_kv + 31) / 32;
    for (int kt = 0; kt < ntiles; kt++) {
        const int j0 = kt * 32;
        // load K & V tiles (32x64 each = 512 float4)
        #pragma unroll
        for (int j = 0; j < 2; j++) {
            int idx4 = t + j*256;
            int jr = idx4 >> 4, c4 = (idx4 & 15) * 4;
            int krow = j0 + jr;
            float4 kv = make_float4(0.f,0.f,0.f,0.f);
            float4 vv = make_float4(0.f,0.f,0.f,0.f);
            if (krow < n_kv) {
                kv = *(const float4*)&kb[(size_t)krow*INNER_ + c4];
                vv = *(const float4*)&vb[(size_t)krow*INNER_ + c4];
            }
            Ks[jr][c4+0]=kv.x; Ks[jr][c4+1]=kv.y; Ks[jr][c4+2]=kv.z; Ks[jr][c4+3]=kv.w;
            Vs[jr][c4+0]=vv.x; Vs[jr][c4+1]=vv.y; Vs[jr][c4+2]=vv.z; Vs[jr][c4+3]=vv.w;
        }
        __syncthreads();

        // scores: 8 keys per thread (j = jq + 4*jj)
        #pragma unroll
        for (int jj = 0; jj < 8; jj++) {
            int j = jq + 4*jj;
            float s = 0.f;
            #pragma unroll
            for (int d = 0; d < 64; d++) s += Qs[r][d] * Ks[j][d];
            Sx[r][j] = (j0 + j < n_kv) ? s * 0.125f : -1e30f;
        }
        __syncthreads();

        // online softmax bookkeeping: one thread per row
        if (t < 64) {
            float m_old = mrow[t];
            float mnew = m_old;
            #pragma unroll 8
            for (int j = 0; j < 32; j++) mnew = fmaxf(mnew, Sx[t][j]);
            float alpha = __expf(m_old - mnew);
            float psum = 0.f;
            #pragma unroll 8
            for (int j = 0; j < 32; j++) {
                float p = __expf(Sx[t][j] - mnew);
                Sx[t][j] = p;
                psum += p;
            }
            mrow[t] = mnew;
            lrow[t] = lrow[t]*alpha + psum;
            arow[t] = alpha;
        }
        __syncthreads();

        // accumulate O: this thread owns dims d = jq + 4*i of row r
        float alpha = arow[r];
        #pragma unroll
        for (int i = 0; i < 16; i++) acc[i] *= alpha;
        #pragma unroll 4
        for (int j = 0; j < 32; j++) {
            float p = Sx[r][j];
            #pragma unroll
            for (int i = 0; i < 16; i++)
                acc[i] += p * Vs[j][jq + 4*i];
        }
        __syncthreads();
    }

    const float inv = 1.f / lrow[r];
    float* orow = O + ((size_t)(b*n_q + q0 + r))*INNER_ + h*DHEAD_ + jq;
    #pragma unroll
    for (int i = 0; i < 16; i++) orow[4*i] = acc[i] * inv;
}

// ---------------- GEGLU: gl = a * gelu_exact(g) ----------------------------
__global__ void geglu_k(const float* __restrict__ ff, float* __restrict__ gl)
{
    int idx = blockIdx.x * 256 + threadIdx.x;     // MTOK*FFI total
    int row = idx / FFI, col = idx - row*FFI;
    float a = ff[(size_t)row*4096 + col];
    float g = ff[(size_t)row*4096 + 2048 + col];
    gl[idx] = a * (0.5f * g * (1.f + erff(g * 0.70710678118654752f)));
}

// ---------------- launch -----------------------------------------------------
extern "C" void kernel_launch(void* const* d_in, const int* in_sizes, int n_in,
                              void* d_out, int out_size)
{
    const float* x    = (const float*)d_in[0];
    const float* ctx  = (const float*)d_in[1];
    const float* gng  = (const float*)d_in[2];
    const float* gnb  = (const float*)d_in[3];
    const float* w_in = (const float*)d_in[4];
    const float* b_in = (const float*)d_in[5];
    const float* ln1g = (const float*)d_in[6];
    const float* ln1b = (const float*)d_in[7];
    const float* wq1  = (const float*)d_in[8];
    const float* wk1  = (const float*)d_in[9];
    const float* wv1  = (const float*)d_in[10];
    const float* wo1  = (const float*)d_in[11];
    const float* bo1  = (const float*)d_in[12];
    const float* ln2g = (const float*)d_in[13];
    const float* ln2b = (const float*)d_in[14];
    const float* wq2  = (const float*)d_in[15];
    const float* wk2  = (const float*)d_in[16];
    const float* wv2  = (const float*)d_in[17];
    const float* wo2  = (const float*)d_in[18];
    const float* bo2  = (const float*)d_in[19];
    const float* ln3g = (const float*)d_in[20];
    const float* ln3b = (const float*)d_in[21];
    const float* wff1 = (const float*)d_in[22];
    const float* bff1 = (const float*)d_in[23];
    const float* wff2 = (const float*)d_in[24];
    const float* bff2 = (const float*)d_in[25];
    const float* wout = (const float*)d_in[26];
    const float* bout = (const float*)d_in[27];
    float* out = (float*)d_out;

    float *hn,*t,*q,*k,*v,*at,*y,*kc,*vc,*ff,*gl,*st;
    cudaGetSymbolAddress((void**)&hn, g_hn);
    cudaGetSymbolAddress((void**)&t,  g_t);
    cudaGetSymbolAddress((void**)&q,  g_q);
    cudaGetSymbolAddress((void**)&k,  g_k);
    cudaGetSymbolAddress((void**)&v,  g_v);
    cudaGetSymbolAddress((void**)&at, g_at);
    cudaGetSymbolAddress((void**)&y,  g_y);
    cudaGetSymbolAddress((void**)&kc, g_kc);
    cudaGetSymbolAddress((void**)&vc, g_vc);
    cudaGetSymbolAddress((void**)&ff, g_ff);
    cudaGetSymbolAddress((void**)&gl, g_gl);
    cudaGetSymbolAddress((void**)&st, g_stat);

    const dim3 tb32(32, 8);
    const dim3 tgrid(NQ/32, CC/32, BB);        // (72, 16, 2)
    const dim3 g512(INNER_/128, MTOK/128);     // (4, 36)
    const dim3 gff1(4096/128, MTOK/128);       // (32, 36)
    const dim3 gctx(INNER_/128, (BB*CTX + 127)/128);   // (4, 2)
    const dim3 gattn(NQ/64, HEADS_, BB);       // (36, 8, 2)

    // GroupNorm + proj_in
    gn_stats_k  <<<BB*32, 256>>>(x, st);
    gn_apply_t_k<<<tgrid, tb32>>>(x, st, gng, gnb, hn);
    sgemm_k<<<g512, 256>>>(hn, w_in, b_in, nullptr, t, MTOK, INNER_, CC);

    // self-attention block
    ln_k<<<MTOK, 128>>>(t, ln1g, ln1b, hn);
    sgemm_k<<<g512, 256>>>(hn, wq1, nullptr, nullptr, q, MTOK, INNER_, INNER_);
    sgemm_k<<<g512, 256>>>(hn, wk1, nullptr, nullptr, k, MTOK, INNER_, INNER_);
    sgemm_k<<<g512, 256>>>(hn, wv1, nullptr, nullptr, v, MTOK, INNER_, INNER_);
    attn_k<<<gattn, 256>>>(q, k, v, at, NQ, NQ);
    sgemm_k<<<g512, 256>>>(at, wo1, bo1, t, t, MTOK, INNER_, INNER_);

    // cross-attention block
    ln_k<<<MTOK, 128>>>(t, ln2g, ln2b, hn);
    sgemm_k<<<g512, 256>>>(hn, wq2, nullptr, nullptr, q, MTOK, INNER_, INNER_);
    sgemm_k<<<gctx, 256>>>(ctx, wk2, nullptr, nullptr, kc, BB*CTX, INNER_, CTXD);
    sgemm_k<<<gctx, 256>>>(ctx, wv2, nullptr, nullptr, vc, BB*CTX, INNER_, CTXD);
    attn_k<<<gattn, 256>>>(q, kc, vc, at, NQ, CTX);
    sgemm_k<<<g512, 256>>>(at, wo2, bo2, t, t, MTOK, INNER_, INNER_);

    // feed-forward (GEGLU)
    ln_k<<<MTOK, 128>>>(t, ln3g, ln3b, hn);
    sgemm_k<<<gff1, 256>>>(hn, wff1, bff1, nullptr, ff, MTOK, 4096, INNER_);
    geglu_k<<<(MTOK*FFI)/256, 256>>>(ff, gl);
    sgemm_k<<<g512, 256>>>(gl, wff2, bff2, t, t, MTOK, INNER_, FFI);

    // proj_out + residual (image layout)
    sgemm_k<<<g512, 256>>>(t, wout, bout, nullptr, y, MTOK, CC, INNER_);
    out_add_k<<<tgrid, tb32>>>(y, x, out);
}

// round 3
// speedup vs baseline: 3.1837x; 3.1837x over previous
#include <cuda_runtime.h>
#include <cstdint>
#include <math.h>

// ---------------- problem constants ----------------
#define BB     2
#define CC     512
#define NQ     2304
#define INNER_ 512
#define HEADS_ 8
#define DHEAD_ 64
#define CTX    77
#define CTXD   768
#define FFI    2048
#define MTOK   4608

// ---------------- scratch (device globals) ---------------------------------
__device__ float g_hn[MTOK*INNER_];
__device__ float g_t [MTOK*INNER_];
__device__ float g_q [MTOK*INNER_];
__device__ float g_k [MTOK*INNER_];
__device__ float g_v [MTOK*INNER_];
__device__ float g_at[MTOK*INNER_];
__device__ float g_y [MTOK*INNER_];
__device__ float g_kc[BB*CTX*INNER_];
__device__ float g_vc[BB*CTX*INNER_];
__device__ float g_ff[MTOK*4096];
__device__ float g_gl[MTOK*FFI];
__device__ float g_stat[BB*32*2];
__device__ float g_s [84934656];            // 16 * 2304 * 2304 attn scores
__device__ float g_vt[16*DHEAD_*NQ];        // per-head transposed V
// transposed weights [N,K]
__device__ float g_wt_in [512*512];
__device__ float g_wtq1  [512*512];
__device__ float g_wtk1  [512*512];
__device__ float g_wtv1  [512*512];
__device__ float g_wto1  [512*512];
__device__ float g_wtq2  [512*512];
__device__ float g_wtk2  [512*768];
__device__ float g_wtv2  [512*768];
__device__ float g_wto2  [512*512];
__device__ float g_wtff1 [4096*512];
__device__ float g_wtff2 [512*2048];
__device__ float g_wtout [512*512];

// ---------------- PTX helpers (baseline-target only) ------------------------
__device__ __forceinline__ uint32_t smem_u32(const void* p) {
    uint32_t a;
    asm("{ .reg .u64 t; cvta.to.shared.u64 t, %1; cvt.u32.u64 %0, t; }"
        : "=r"(a) : "l"(p));
    return a;
}
__device__ __forceinline__ uint32_t f2tf(float x) {
    uint32_t r;
    asm("cvt.rna.tf32.f32 %0, %1;" : "=r"(r) : "f"(x));
    return r;
}
__device__ __forceinline__ void mma_t(float* c, const uint32_t* a, const uint32_t* b) {
    asm volatile("mma.sync.aligned.m16n8k8.row.col.f32.tf32.tf32.f32 "
        "{%0,%1,%2,%3}, {%4,%5,%6,%7}, {%8,%9}, {%0,%1,%2,%3};"
        : "+f"(c[0]), "+f"(c[1]), "+f"(c[2]), "+f"(c[3])
        : "r"(a[0]), "r"(a[1]), "r"(a[2]), "r"(a[3]), "r"(b[0]), "r"(b[1]));
}
__device__ __forceinline__ void cp16(uint32_t dst, const float* src, bool valid) {
    int sz = valid ? 16 : 0;
    asm volatile("cp.async.cg.shared.global [%0], [%1], 16, %2;"
                 :: "r"(dst), "l"(src), "r"(sz) : "memory");
}
#define CP_COMMIT() asm volatile("cp.async.commit_group;" ::: "memory")
#define CP_WAIT(n)  asm volatile("cp.async.wait_group %0;" :: "n"(n) : "memory")

// ---------------- tf32 mma.sync GEMM ----------------------------------------
// C = A[M,K](lda) @ Bt[N,K](ldb)^T (+bias)(+res). BM=128, BN template, BK=32.
// z-batched: base += (z>>3)*sXo + (z&7)*sXi.  Row stride in smem: 36 floats.
template<int BN>
__global__ void __launch_bounds__(256)
tgemm_k(const float* __restrict__ A, const float* __restrict__ Bt,
        const float* __restrict__ bias, const float* __restrict__ res,
        float* __restrict__ C,
        int M, int K, int lda, int ldb, int ldc,
        size_t sAo, size_t sAi, size_t sBo, size_t sBi, size_t sCo, size_t sCi)
{
    extern __shared__ float smem[];
    const int t = threadIdx.x, wid = t >> 5, lane = t & 31;
    const int bn = blockIdx.x * BN, bm = blockIdx.y * 128;
    const int zb = blockIdx.z >> 3, zh = blockIdx.z & 7;
    A  += zb * sAo + zh * sAi;
    Bt += zb * sBo + zh * sBi;
    C  += zb * sCo + zh * sCi;

    constexpr int WN   = BN / 2;      // warp tile N
    constexpr int NT   = WN / 8;      // n-tiles per warp
    constexpr int AFL  = 128 * 36;    // A floats per buffer
    constexpr int BFL  = BN * 36;
    constexpr int STR  = AFL + BFL;

    const int mw = wid & 3, nw = wid >> 2;
    const int gp = lane >> 2, qd = lane & 3;      // group / quad

    float acc[2][NT][4];
    #pragma unroll
    for (int i = 0; i < 2; i++)
        #pragma unroll
        for (int j = 0; j < NT; j++)
            #pragma unroll
            for (int c = 0; c < 4; c++) acc[i][j][c] = 0.f;

    const uint32_t sbase = smem_u32(smem);

    auto load_tile = [&](int kt, int buf) {
        const int k0 = kt * 32;
        const uint32_t offA = sbase + buf * STR * 4;
        const uint32_t offB = offA + AFL * 4;
        #pragma unroll
        for (int i = 0; i < 4; i++) {
            int idx = t + i * 256, row = idx >> 3, q = idx & 7;
            bool ok = (bm + row) < M;
            const float* src = &A[(size_t)(ok ? bm + row : 0) * lda + k0 + q * 4];
            cp16(offA + (row * 36 + q * 4) * 4, src, ok);
        }
        #pragma unroll
        for (int i = 0; i < BN / 32; i++) {
            int idx = t + i * 256, row = idx >> 3, q = idx & 7;
            cp16(offB + (row * 36 + q * 4) * 4,
                 &Bt[(size_t)(bn + row) * ldb + k0 + q * 4], true);
        }
        CP_COMMIT();
    };

    const int KT = K / 32;
    load_tile(0, 0);

    for (int kt = 0; kt < KT; kt++) {
        const int cur = kt & 1;
        if (kt + 1 < KT) { load_tile(kt + 1, cur ^ 1); CP_WAIT(1); }
        else             { CP_WAIT(0); }
        __syncthreads();

        const float* As = smem + cur * STR;
        const float* Bs = As + AFL;
        #pragma unroll
        for (int ks = 0; ks < 4; ks++) {
            const int kc = ks * 8 + qd;
            uint32_t af[2][4];
            #pragma unroll
            for (int mt = 0; mt < 2; mt++) {
                const int r = mw * 32 + mt * 16 + gp;
                af[mt][0] = f2tf(As[(r    ) * 36 + kc    ]);
                af[mt][1] = f2tf(As[(r + 8) * 36 + kc    ]);
                af[mt][2] = f2tf(As[(r    ) * 36 + kc + 4]);
                af[mt][3] = f2tf(As[(r + 8) * 36 + kc + 4]);
            }
            uint32_t bf[NT][2];
            #pragma unroll
            for (int nt = 0; nt < NT; nt++) {
                const int n = nw * WN + nt * 8 + gp;
                bf[nt][0] = f2tf(Bs[n * 36 + ks * 8 + qd    ]);
                bf[nt][1] = f2tf(Bs[n * 36 + ks * 8 + qd + 4]);
            }
            #pragma unroll
            for (int mt = 0; mt < 2; mt++)
                #pragma unroll
                for (int nt = 0; nt < NT; nt++)
                    mma_t(acc[mt][nt], af[mt], bf[nt]);
        }
        __syncthreads();
    }

    // epilogue
    #pragma unroll
    for (int mt = 0; mt < 2; mt++) {
        const int r0 = bm + mw * 32 + mt * 16 + gp;
        #pragma unroll
        for (int nt = 0; nt < NT; nt++) {
            const int col = bn + nw * WN + nt * 8 + qd * 2;
            float2 lo = make_float2(acc[mt][nt][0], acc[mt][nt][1]);
            float2 hi = make_float2(acc[mt][nt][2], acc[mt][nt][3]);
            if (bias) {
                const float2 b2 = *(const float2*)&bias[col];
                lo.x += b2.x; lo.y += b2.y; hi.x += b2.x; hi.y += b2.y;
            }
            if (r0 < M) {
                if (res) {
                    const float2 r2 = *(const float2*)&res[(size_t)r0 * ldc + col];
                    lo.x += r2.x; lo.y += r2.y;
                }
                *(float2*)&C[(size_t)r0 * ldc + col] = lo;
            }
            if (r0 + 8 < M) {
                if (res) {
                    const float2 r2 = *(const float2*)&res[(size_t)(r0 + 8) * ldc + col];
                    hi.x += r2.x; hi.y += r2.y;
                }
                *(float2*)&C[(size_t)(r0 + 8) * ldc + col] = hi;
            }
        }
    }
}

// ---------------- weight transpose: W[K,N] -> Wt[N,K] ----------------------
__global__ void tr_k(const float* __restrict__ W, float* __restrict__ Wt, int K, int N)
{
    __shared__ float tl[32][33];
    int k0 = blockIdx.x * 32, n0 = blockIdx.y * 32;
    int tx = threadIdx.x, ty = threadIdx.y;
    #pragma unroll
    for (int i = 0; i < 4; i++)
        tl[ty + i * 8][tx] = W[(size_t)(k0 + ty + i * 8) * N + n0 + tx];
    __syncthreads();
    #pragma unroll
    for (int i = 0; i < 4; i++)
        Wt[(size_t)(n0 + ty + i * 8) * K + k0 + tx] = tl[tx][ty + i * 8];
}

// ---------------- per-head V transpose: V[b*2304, 512] -> Vt[bh][64][2304] --
__global__ void vtr_k(const float* __restrict__ V, float* __restrict__ Vt)
{
    __shared__ float tl[32][33];
    int j0 = blockIdx.x * 32, d0 = blockIdx.y * 32, z = blockIdx.z;
    int b = z >> 3, h = z & 7;
    int tx = threadIdx.x, ty = threadIdx.y;
    #pragma unroll
    for (int i = 0; i < 4; i++)
        tl[ty + i * 8][tx] = V[((size_t)b * NQ + j0 + ty + i * 8) * INNER_ + h * DHEAD_ + d0 + tx];
    __syncthreads();
    #pragma unroll
    for (int i = 0; i < 4; i++)
        Vt[(size_t)z * DHEAD_ * NQ + (size_t)(d0 + ty + i * 8) * NQ + j0 + tx] = tl[tx][ty + i * 8];
}

// ---------------- row softmax over 2304 cols (with 0.125 scale) ------------
__global__ void softmax_k(float* __restrict__ S)
{
    float* p = S + (size_t)blockIdx.x * NQ;
    const int t = threadIdx.x;
    float v[9];
    float m = -1e30f;
    #pragma unroll
    for (int i = 0; i < 9; i++) { v[i] = p[t + i * 256]; m = fmaxf(m, v[i]); }
    for (int o = 16; o; o >>= 1) m = fmaxf(m, __shfl_xor_sync(~0u, m, o));
    __shared__ float sm[8], ss[8];
    if ((t & 31) == 0) sm[t >> 5] = m;
    __syncthreads();
    float mm = sm[0];
    #pragma unroll
    for (int i = 1; i < 8; i++) mm = fmaxf(mm, sm[i]);
    float s = 0.f;
    #pragma unroll
    for (int i = 0; i < 9; i++) { v[i] = __expf((v[i] - mm) * 0.125f); s += v[i]; }
    for (int o = 16; o; o >>= 1) s += __shfl_xor_sync(~0u, s, o);
    if ((t & 31) == 0) ss[t >> 5] = s;
    __syncthreads();
    float tot = 0.f;
    #pragma unroll
    for (int i = 0; i < 8; i++) tot += ss[i];
    const float inv = 1.f / tot;
    #pragma unroll
    for (int i = 0; i < 9; i++) p[t + i * 256] = v[i] * inv;
}

// ---------------- GroupNorm stats -------------------------------------------
__global__ void gn_stats_k(const float* __restrict__ x, float* __restrict__ st)
{
    int bg = blockIdx.x, b = bg >> 5, g = bg & 31;
    const float* base = x + ((size_t)b * CC + (size_t)g * 16) * NQ;
    float s = 0.f, s2 = 0.f;
    for (int i = threadIdx.x; i < 16 * NQ; i += 256) {
        float v = base[i]; s += v; s2 += v * v;
    }
    for (int o = 16; o > 0; o >>= 1) {
        s  += __shfl_down_sync(~0u, s,  o);
        s2 += __shfl_down_sync(~0u, s2, o);
    }
    __shared__ float sh1[8], sh2[8];
    int w = threadIdx.x >> 5, lane = threadIdx.x & 31;
    if (lane == 0) { sh1[w] = s; sh2[w] = s2; }
    __syncthreads();
    if (threadIdx.x == 0) {
        float S = 0.f, S2 = 0.f;
        for (int i = 0; i < 8; i++) { S += sh1[i]; S2 += sh2[i]; }
        float mean = S / (16.f * NQ);
        float var  = S2 / (16.f * NQ) - mean * mean;
        st[bg * 2]     = mean;
        st[bg * 2 + 1] = rsqrtf(var + 1e-6f);
    }
}

// --------- GroupNorm apply + NCHW -> [b,n,c] transpose ----------------------
__global__ void gn_apply_t_k(const float* __restrict__ x, const float* __restrict__ st,
                             const float* __restrict__ gg, const float* __restrict__ gb,
                             float* __restrict__ o)
{
    __shared__ float tile[32][33];
    int n0 = blockIdx.x * 32, c0 = blockIdx.y * 32, b = blockIdx.z;
    int tx = threadIdx.x, ty = threadIdx.y;
    #pragma unroll
    for (int i = 0; i < 4; i++) {
        int c = c0 + ty + i * 8;
        int g = c >> 4;
        float mean = st[(b * 32 + g) * 2], rstd = st[(b * 32 + g) * 2 + 1];
        float v = x[((size_t)b * CC + c) * NQ + n0 + tx];
        tile[ty + i * 8][tx] = (v - mean) * rstd * gg[c] + gb[c];
    }
    __syncthreads();
    #pragma unroll
    for (int i = 0; i < 4; i++) {
        int n = n0 + ty + i * 8;
        o[((size_t)b * NQ + n) * INNER_ + c0 + tx] = tile[tx][ty + i * 8];
    }
}

// --------- final: [b,n,c] -> NCHW + residual --------------------------------
__global__ void out_add_k(const float* __restrict__ yb, const float* __restrict__ x,
                          float* __restrict__ o)
{
    __shared__ float tile[32][33];
    int n0 = blockIdx.x * 32, c0 = blockIdx.y * 32, b = blockIdx.z;
    int tx = threadIdx.x, ty = threadIdx.y;
    #pragma unroll
    for (int i = 0; i < 4; i++) {
        int n = n0 + ty + i * 8;
        tile[ty + i * 8][tx] = yb[((size_t)b * NQ + n) * INNER_ + c0 + tx];
    }
    __syncthreads();
    #pragma unroll
    for (int i = 0; i < 4; i++) {
        int c = c0 + ty + i * 8;
        size_t idx = ((size_t)b * CC + c) * NQ + n0 + tx;
        o[idx] = tile[tx][ty + i * 8] + x[idx];
    }
}

// ---------------- LayerNorm over 512 ----------------------------------------
__global__ void ln_k(const float* __restrict__ X, const float* __restrict__ g,
                     const float* __restrict__ bb, float* __restrict__ O)
{
    int row = blockIdx.x;
    int t = threadIdx.x;
    const float4 v = ((const float4*)(X + (size_t)row * INNER_))[t];
    float s  = v.x + v.y + v.z + v.w;
    float s2 = v.x*v.x + v.y*v.y + v.z*v.z + v.w*v.w;
    for (int o = 16; o > 0; o >>= 1) {
        s  += __shfl_down_sync(~0u, s,  o);
        s2 += __shfl_down_sync(~0u, s2, o);
    }
    __shared__ float sh1[4], sh2[4];
    int w = t >> 5, lane = t & 31;
    if (lane == 0) { sh1[w] = s; sh2[w] = s2; }
    __syncthreads();
    if (t == 0) {
        float S = sh1[0]+sh1[1]+sh1[2]+sh1[3];
        float S2 = sh2[0]+sh2[1]+sh2[2]+sh2[3];
        float mean = S / 512.f;
        float var  = S2 / 512.f - mean * mean;
        sh1[0] = mean; sh2[0] = rsqrtf(var + 1e-5f);
    }
    __syncthreads();
    float mean = sh1[0], rstd = sh2[0];
    float4 g4 = ((const float4*)g)[t];
    float4 b4 = ((const float4*)bb)[t];
    float4 o;
    o.x = (v.x-mean)*rstd*g4.x + b4.x;
    o.y = (v.y-mean)*rstd*g4.y + b4.y;
    o.z = (v.z-mean)*rstd*g4.z + b4.z;
    o.w = (v.w-mean)*rstd*g4.w + b4.w;
    ((float4*)(O + (size_t)row * INNER_))[t] = o;
}

// ---------------- fp32 flash attention (cross-attn only) --------------------
__global__ void __launch_bounds__(256) attn_k(
    const float* __restrict__ Q, const float* __restrict__ Kb,
    const float* __restrict__ Vb, float* __restrict__ O,
    int n_q, int n_kv)
{
    __shared__ float Qs[64][68];
    __shared__ float Ks[32][68];
    __shared__ float Vs[32][68];
    __shared__ float Sx[64][33];
    __shared__ float mrow[64], lrow[64], arow[64];

    const int t  = threadIdx.x;
    const int h  = blockIdx.y, b = blockIdx.z;
    const int q0 = blockIdx.x * 64;
    const float* qb = Q  + ((size_t)b * n_q ) * INNER_ + h * DHEAD_;
    const float* kb = Kb + ((size_t)b * n_kv) * INNER_ + h * DHEAD_;
    const float* vb = Vb + ((size_t)b * n_kv) * INNER_ + h * DHEAD_;

    #pragma unroll
    for (int j = 0; j < 4; j++) {
        int idx4 = t + j * 256;
        int r = idx4 >> 4, c4 = (idx4 & 15) * 4;
        float4 v = *(const float4*)&qb[(size_t)(q0 + r) * INNER_ + c4];
        Qs[r][c4+0]=v.x; Qs[r][c4+1]=v.y; Qs[r][c4+2]=v.z; Qs[r][c4+3]=v.w;
    }
    if (t < 64) { mrow[t] = -1e30f; lrow[t] = 0.f; }

    float acc[16];
    #pragma unroll
    for (int i = 0; i < 16; i++) acc[i] = 0.f;
    const int r  = t >> 2;
    const int jq = t & 3;

    const int ntiles = (n_kv + 31) / 32;
    for (int kt = 0; kt < ntiles; kt++) {
        const int j0 = kt * 32;
        #pragma unroll
        for (int j = 0; j < 2; j++) {
            int idx4 = t + j * 256;
            int jr = idx4 >> 4, c4 = (idx4 & 15) * 4;
            int krow = j0 + jr;
            float4 kv = make_float4(0.f,0.f,0.f,0.f);
            float4 vv = make_float4(0.f,0.f,0.f,0.f);
            if (krow < n_kv) {
                kv = *(const float4*)&kb[(size_t)krow * INNER_ + c4];
                vv = *(const float4*)&vb[(size_t)krow * INNER_ + c4];
            }
            Ks[jr][c4+0]=kv.x; Ks[jr][c4+1]=kv.y; Ks[jr][c4+2]=kv.z; Ks[jr][c4+3]=kv.w;
            Vs[jr][c4+0]=vv.x; Vs[jr][c4+1]=vv.y; Vs[jr][c4+2]=vv.z; Vs[jr][c4+3]=vv.w;
        }
        __syncthreads();
        #pragma unroll
        for (int jj = 0; jj < 8; jj++) {
            int j = jq + 4*jj;
            float s = 0.f;
            #pragma unroll
            for (int d = 0; d < 64; d++) s += Qs[r][d] * Ks[j][d];
            Sx[r][j] = (j0 + j < n_kv) ? s * 0.125f : -1e30f;
        }
        __syncthreads();
        if (t < 64) {
            float m_old = mrow[t];
            float mnew = m_old;
            #pragma unroll 8
            for (int j = 0; j < 32; j++) mnew = fmaxf(mnew, Sx[t][j]);
            float alpha = __expf(m_old - mnew);
            float psum = 0.f;
            #pragma unroll 8
            for (int j = 0; j < 32; j++) {
                float p = __expf(Sx[t][j] - mnew);
                Sx[t][j] = p; psum += p;
            }
            mrow[t] = mnew;
            lrow[t] = lrow[t]*alpha + psum;
            arow[t] = alpha;
        }
        __syncthreads();
        float alpha = arow[r];
        #pragma unroll
        for (int i = 0; i < 16; i++) acc[i] *= alpha;
        #pragma unroll 4
        for (int j = 0; j < 32; j++) {
            float p = Sx[r][j];
            #pragma unroll
            for (int i = 0; i < 16; i++)
                acc[i] += p * Vs[j][jq + 4*i];
        }
        __syncthreads();
    }
    const float inv = 1.f / lrow[r];
    float* orow = O + ((size_t)(b * n_q + q0 + r)) * INNER_ + h * DHEAD_ + jq;
    #pragma unroll
    for (int i = 0; i < 16; i++) orow[4*i] = acc[i] * inv;
}

// ---------------- GEGLU ------------------------------------------------------
__global__ void geglu_k(const float* __restrict__ ff, float* __restrict__ gl)
{
    int idx = blockIdx.x * 256 + threadIdx.x;
    int row = idx / FFI, col = idx - row * FFI;
    float a = ff[(size_t)row * 4096 + col];
    float g = ff[(size_t)row * 4096 + 2048 + col];
    gl[idx] = a * (0.5f * g * (1.f + erff(g * 0.70710678118654752f)));
}

// ---------------- launch ------------------------------------------------------
extern "C" void kernel_launch(void* const* d_in, const int* in_sizes, int n_in,
                              void* d_out, int out_size)
{
    const float* x    = (const float*)d_in[0];
    const float* ctx  = (const float*)d_in[1];
    const float* gng  = (const float*)d_in[2];
    const float* gnb  = (const float*)d_in[3];
    const float* w_in = (const float*)d_in[4];
    const float* b_in = (const float*)d_in[5];
    const float* ln1g = (const float*)d_in[6];
    const float* ln1b = (const float*)d_in[7];
    const float* wq1  = (const float*)d_in[8];
    const float* wk1  = (const float*)d_in[9];
    const float* wv1  = (const float*)d_in[10];
    const float* wo1  = (const float*)d_in[11];
    const float* bo1  = (const float*)d_in[12];
    const float* ln2g = (const float*)d_in[13];
    const float* ln2b = (const float*)d_in[14];
    const float* wq2  = (const float*)d_in[15];
    const float* wk2  = (const float*)d_in[16];
    const float* wv2  = (const float*)d_in[17];
    const float* wo2  = (const float*)d_in[18];
    const float* bo2  = (const float*)d_in[19];
    const float* ln3g = (const float*)d_in[20];
    const float* ln3b = (const float*)d_in[21];
    const float* wff1 = (const float*)d_in[22];
    const float* bff1 = (const float*)d_in[23];
    const float* wff2 = (const float*)d_in[24];
    const float* bff2 = (const float*)d_in[25];
    const float* wout = (const float*)d_in[26];
    const float* bout = (const float*)d_in[27];
    float* out = (float*)d_out;

    float *hn,*t_,*q,*k,*v,*at,*y,*kc,*vc,*ff,*gl,*st,*S,*vt;
    float *wt_in,*wtq1,*wtk1,*wtv1,*wto1,*wtq2,*wtk2,*wtv2,*wto2,*wtff1,*wtff2,*wtout;
    cudaGetSymbolAddress((void**)&hn, g_hn);
    cudaGetSymbolAddress((void**)&t_, g_t);
    cudaGetSymbolAddress((void**)&q,  g_q);
    cudaGetSymbolAddress((void**)&k,  g_k);
    cudaGetSymbolAddress((void**)&v,  g_v);
    cudaGetSymbolAddress((void**)&at, g_at);
    cudaGetSymbolAddress((void**)&y,  g_y);
    cudaGetSymbolAddress((void**)&kc, g_kc);
    cudaGetSymbolAddress((void**)&vc, g_vc);
    cudaGetSymbolAddress((void**)&ff, g_ff);
    cudaGetSymbolAddress((void**)&gl, g_gl);
    cudaGetSymbolAddress((void**)&st, g_stat);
    cudaGetSymbolAddress((void**)&S,  g_s);
    cudaGetSymbolAddress((void**)&vt, g_vt);
    cudaGetSymbolAddress((void**)&wt_in, g_wt_in);
    cudaGetSymbolAddress((void**)&wtq1, g_wtq1);
    cudaGetSymbolAddress((void**)&wtk1, g_wtk1);
    cudaGetSymbolAddress((void**)&wtv1, g_wtv1);
    cudaGetSymbolAddress((void**)&wto1, g_wto1);
    cudaGetSymbolAddress((void**)&wtq2, g_wtq2);
    cudaGetSymbolAddress((void**)&wtk2, g_wtk2);
    cudaGetSymbolAddress((void**)&wtv2, g_wtv2);
    cudaGetSymbolAddress((void**)&wto2, g_wto2);
    cudaGetSymbolAddress((void**)&wtff1, g_wtff1);
    cudaGetSymbolAddress((void**)&wtff2, g_wtff2);
    cudaGetSymbolAddress((void**)&wtout, g_wtout);

    // dynamic smem: 2 buffers of (128*36 + BN*36) floats
    const int SM128 = 2 * (128 * 36 + 128 * 36) * 4;   // 73728
    const int SM64  = 2 * (128 * 36 +  64 * 36) * 4;   // 55296
    cudaFuncSetAttribute(tgemm_k<128>, cudaFuncAttributeMaxDynamicSharedMemorySize, SM128);
    cudaFuncSetAttribute(tgemm_k<64>,  cudaFuncAttributeMaxDynamicSharedMemorySize, SM64);

    const dim3 tb(32, 8);
    const size_t X = (size_t)NQ * NQ;

    // weight transposes
    tr_k<<<dim3(16, 16), tb>>>(w_in, wt_in, 512, 512);
    tr_k<<<dim3(16, 16), tb>>>(wq1, wtq1, 512, 512);
    tr_k<<<dim3(16, 16), tb>>>(wk1, wtk1, 512, 512);
    tr_k<<<dim3(16, 16), tb>>>(wv1, wtv1, 512, 512);
    tr_k<<<dim3(16, 16), tb>>>(wo1, wto1, 512, 512);
    tr_k<<<dim3(16, 16), tb>>>(wq2, wtq2, 512, 512);
    tr_k<<<dim3(24, 16), tb>>>(wk2, wtk2, 768, 512);
    tr_k<<<dim3(24, 16), tb>>>(wv2, wtv2, 768, 512);
    tr_k<<<dim3(16, 16), tb>>>(wo2, wto2, 512, 512);
    tr_k<<<dim3(16, 128), tb>>>(wff1, wtff1, 512, 4096);
    tr_k<<<dim3(64, 16), tb>>>(wff2, wtff2, 2048, 512);
    tr_k<<<dim3(16, 16), tb>>>(wout, wtout, 512, 512);

    // GroupNorm + proj_in
    gn_stats_k  <<<BB*32, 256>>>(x, st);
    gn_apply_t_k<<<dim3(72, 16, 2), tb>>>(x, st, gng, gnb, hn);
    tgemm_k<128><<<dim3(4, 36, 1), 256, SM128>>>(hn, wt_in, b_in, nullptr, t_,
        MTOK, 512, 512, 512, 512, 0,0,0,0,0,0);

    // self-attention
    ln_k<<<MTOK, 128>>>(t_, ln1g, ln1b, hn);
    tgemm_k<128><<<dim3(4, 36, 1), 256, SM128>>>(hn, wtq1, nullptr, nullptr, q,
        MTOK, 512, 512, 512, 512, 0,0,0,0,0,0);
    tgemm_k<128><<<dim3(4, 36, 1), 256, SM128>>>(hn, wtk1, nullptr, nullptr, k,
        MTOK, 512, 512, 512, 512, 0,0,0,0,0,0);
    tgemm_k<128><<<dim3(4, 36, 1), 256, SM128>>>(hn, wtv1, nullptr, nullptr, v,
        MTOK, 512, 512, 512, 512, 0,0,0,0,0,0);
    // S = Q @ K^T per (b,h)
    tgemm_k<128><<<dim3(18, 18, 16), 256, SM128>>>(q, k, nullptr, nullptr, S,
        NQ, 64, 512, 512, NQ,
        (size_t)NQ*512, 64, (size_t)NQ*512, 64, 8*X, X);
    softmax_k<<<16*NQ, 256>>>(S);
    vtr_k<<<dim3(72, 2, 16), tb>>>(v, vt);
    // O = P @ V per (b,h)
    tgemm_k<64><<<dim3(1, 18, 16), 256, SM64>>>(S, vt, nullptr, nullptr, at,
        NQ, NQ, NQ, NQ, 512,
        8*X, X, (size_t)8*64*NQ, (size_t)64*NQ, (size_t)NQ*512, 64);
    tgemm_k<128><<<dim3(4, 36, 1), 256, SM128>>>(at, wto1, bo1, t_, t_,
        MTOK, 512, 512, 512, 512, 0,0,0,0,0,0);

    // cross-attention
    ln_k<<<MTOK, 128>>>(t_, ln2g, ln2b, hn);
    tgemm_k<128><<<dim3(4, 36, 1), 256, SM128>>>(hn, wtq2, nullptr, nullptr, q,
        MTOK, 512, 512, 512, 512, 0,0,0,0,0,0);
    tgemm_k<128><<<dim3(4, 2, 1), 256, SM128>>>(ctx, wtk2, nullptr, nullptr, kc,
        BB*CTX, 768, 768, 768, 512, 0,0,0,0,0,0);
    tgemm_k<128><<<dim3(4, 2, 1), 256, SM128>>>(ctx, wtv2, nullptr, nullptr, vc,
        BB*CTX, 768, 768, 768, 512, 0,0,0,0,0,0);
    attn_k<<<dim3(36, 8, 2), 256>>>(q, kc, vc, at, NQ, CTX);
    tgemm_k<128><<<dim3(4, 36, 1), 256, SM128>>>(at, wto2, bo2, t_, t_,
        MTOK, 512, 512, 512, 512, 0,0,0,0,0,0);

    // feed-forward (GEGLU)
    ln_k<<<MTOK, 128>>>(t_, ln3g, ln3b, hn);
    tgemm_k<128><<<dim3(32, 36, 1), 256, SM128>>>(hn, wtff1, bff1, nullptr, ff,
        MTOK, 512, 512, 512, 4096, 0,0,0,0,0,0);
    geglu_k<<<(MTOK*FFI)/256, 256>>>(ff, gl);
    tgemm_k<128><<<dim3(4, 36, 1), 256, SM128>>>(gl, wtff2, bff2, t_, t_,
        MTOK, 2048, 2048, 2048, 512, 0,0,0,0,0,0);

    // proj_out + residual
    tgemm_k<128><<<dim3(4, 36, 1), 256, SM128>>>(t_, wtout, bout, nullptr, y,
        MTOK, 512, 512, 512, 512, 0,0,0,0,0,0);
    out_add_k<<<dim3(72, 16, 2), tb>>>(y, x, out);
}

// round 4
// speedup vs baseline: 4.3894x; 1.3787x over previous
#include <cuda_runtime.h>
#include <cstdint>
#include <math.h>

// ---------------- problem constants ----------------
#define BB     2
#define CC     512
#define NQ     2304
#define INNER_ 512
#define HEADS_ 8
#define DHEAD_ 64
#define CTX    77
#define CTXD   768
#define FFI    2048
#define MTOK   4608

// ---------------- scratch (device globals) ---------------------------------
__device__ float g_hn  [MTOK*INNER_];
__device__ float g_t   [MTOK*INNER_];
__device__ float g_q   [MTOK*INNER_];
__device__ float g_at  [MTOK*INNER_];
__device__ float g_y   [MTOK*INNER_];
__device__ float g_qkv [MTOK*1536];
__device__ float g_kvc [160*1024];
__device__ float g_ff  [MTOK*4096];
__device__ float g_gl  [MTOK*FFI];
__device__ float g_stat[BB*32*2];
__device__ float g_vt  [16*DHEAD_*NQ];
// transposed weights [N,K]
__device__ float g_wt_in [512*512];
__device__ float g_wqkv  [1536*512];
__device__ float g_wto1  [512*512];
__device__ float g_wtq2  [512*512];
__device__ float g_wtkv2 [1024*768];
__device__ float g_wto2  [512*512];
__device__ float g_wtff1 [4096*512];
__device__ float g_wtff2 [512*2048];
__device__ float g_wtout [512*512];

// ---------------- PTX helpers ------------------------------------------------
__device__ __forceinline__ uint32_t smem_u32(const void* p) {
    uint32_t a;
    asm("{ .reg .u64 t; cvta.to.shared.u64 t, %1; cvt.u32.u64 %0, t; }"
        : "=r"(a) : "l"(p));
    return a;
}
__device__ __forceinline__ uint32_t f2tf(float x) {
    uint32_t r;
    asm("cvt.rna.tf32.f32 %0, %1;" : "=r"(r) : "f"(x));
    return r;
}
__device__ __forceinline__ void mma_t(float* c, const uint32_t* a, const uint32_t* b) {
    asm volatile("mma.sync.aligned.m16n8k8.row.col.f32.tf32.tf32.f32 "
        "{%0,%1,%2,%3}, {%4,%5,%6,%7}, {%8,%9}, {%0,%1,%2,%3};"
        : "+f"(c[0]), "+f"(c[1]), "+f"(c[2]), "+f"(c[3])
        : "r"(a[0]), "r"(a[1]), "r"(a[2]), "r"(a[3]), "r"(b[0]), "r"(b[1]));
}
__device__ __forceinline__ void cp16(uint32_t dst, const float* src, bool valid) {
    int sz = valid ? 16 : 0;
    asm volatile("cp.async.cg.shared.global [%0], [%1], 16, %2;"
                 :: "r"(dst), "l"(src), "r"(sz) : "memory");
}
#define CP_COMMIT() asm volatile("cp.async.commit_group;" ::: "memory")
#define CP_WAIT(n)  asm volatile("cp.async.wait_group %0;" :: "n"(n) : "memory")
#define U32(x) (*(const uint32_t*)&(x))

// ---------------- tf32 mma.sync GEMM ----------------------------------------
// C = A[M,K](lda) @ Bt[N,K](ldb)^T (+bias)(+res). BM=128, BN template, BK=32.
template<int BN>
__global__ void __launch_bounds__(256)
tgemm_k(const float* __restrict__ A, const float* __restrict__ Bt,
        const float* __restrict__ bias, const float* __restrict__ res,
        float* __restrict__ C,
        int M, int K, int lda, int ldb, int ldc)
{
    extern __shared__ float smem[];
    const int t = threadIdx.x, wid = t >> 5, lane = t & 31;
    const int bn = blockIdx.x * BN, bm = blockIdx.y * 128;

    constexpr int WN  = BN / 2;
    constexpr int NT  = WN / 8;
    constexpr int AFL = 128 * 36;
    constexpr int BFL = BN * 36;
    constexpr int STR = AFL + BFL;

    const int mw = wid & 3, nw = wid >> 2;
    const int gp = lane >> 2, qd = lane & 3;

    float acc[2][NT][4];
    #pragma unroll
    for (int i = 0; i < 2; i++)
        #pragma unroll
        for (int j = 0; j < NT; j++)
            #pragma unroll
            for (int c = 0; c < 4; c++) acc[i][j][c] = 0.f;

    const uint32_t sbase = smem_u32(smem);

    auto load_tile = [&](int kt, int buf) {
        const int k0 = kt * 32;
        const uint32_t offA = sbase + buf * STR * 4;
        const uint32_t offB = offA + AFL * 4;
        #pragma unroll
        for (int i = 0; i < 4; i++) {
            int idx = t + i * 256, row = idx >> 3, q = idx & 7;
            bool ok = (bm + row) < M;
            const float* src = &A[(size_t)(ok ? bm + row : 0) * lda + k0 + q * 4];
            cp16(offA + (row * 36 + q * 4) * 4, src, ok);
        }
        #pragma unroll
        for (int i = 0; i < BN / 32; i++) {
            int idx = t + i * 256, row = idx >> 3, q = idx & 7;
            cp16(offB + (row * 36 + q * 4) * 4,
                 &Bt[(size_t)(bn + row) * ldb + k0 + q * 4], true);
        }
        CP_COMMIT();
    };

    const int KT = K / 32;
    load_tile(0, 0);

    for (int kt = 0; kt < KT; kt++) {
        const int cur = kt & 1;
        if (kt + 1 < KT) { load_tile(kt + 1, cur ^ 1); CP_WAIT(1); }
        else             { CP_WAIT(0); }
        __syncthreads();

        const float* As = smem + cur * STR;
        const float* Bs = As + AFL;
        #pragma unroll
        for (int ks = 0; ks < 4; ks++) {
            const int kc = ks * 8 + qd;
            uint32_t af[2][4];
            #pragma unroll
            for (int mt = 0; mt < 2; mt++) {
                const int r = mw * 32 + mt * 16 + gp;
                af[mt][0] = U32(As[(r    ) * 36 + kc    ]);
                af[mt][1] = U32(As[(r + 8) * 36 + kc    ]);
                af[mt][2] = U32(As[(r    ) * 36 + kc + 4]);
                af[mt][3] = U32(As[(r + 8) * 36 + kc + 4]);
            }
            uint32_t bf[NT][2];
            #pragma unroll
            for (int nt = 0; nt < NT; nt++) {
                const int n = nw * WN + nt * 8 + gp;
                bf[nt][0] = U32(Bs[n * 36 + kc    ]);
                bf[nt][1] = U32(Bs[n * 36 + kc + 4]);
            }
            #pragma unroll
            for (int mt = 0; mt < 2; mt++)
                #pragma unroll
                for (int nt = 0; nt < NT; nt++)
                    mma_t(acc[mt][nt], af[mt], bf[nt]);
        }
        __syncthreads();
    }

    #pragma unroll
    for (int mt = 0; mt < 2; mt++) {
        const int r0 = bm + mw * 32 + mt * 16 + gp;
        #pragma unroll
        for (int nt = 0; nt < NT; nt++) {
            const int col = bn + nw * WN + nt * 8 + qd * 2;
            float2 lo = make_float2(acc[mt][nt][0], acc[mt][nt][1]);
            float2 hi = make_float2(acc[mt][nt][2], acc[mt][nt][3]);
            if (bias) {
                const float2 b2 = *(const float2*)&bias[col];
                lo.x += b2.x; lo.y += b2.y; hi.x += b2.x; hi.y += b2.y;
            }
            if (r0 < M) {
                if (res) {
                    const float2 r2 = *(const float2*)&res[(size_t)r0 * ldc + col];
                    lo.x += r2.x; lo.y += r2.y;
                }
                *(float2*)&C[(size_t)r0 * ldc + col] = lo;
            }
            if (r0 + 8 < M) {
                if (res) {
                    const float2 r2 = *(const float2*)&res[(size_t)(r0 + 8) * ldc + col];
                    hi.x += r2.x; hi.y += r2.y;
                }
                *(float2*)&C[(size_t)(r0 + 8) * ldc + col] = hi;
            }
        }
    }
}

// ---------------- flash self-attention (tf32 mma) ----------------------------
// grid (NQ/128, 8, 2). QKV [b*NQ][1536] (q@0, k@512). Vt [16][64][NQ].
__global__ void __launch_bounds__(256, 2) fattn_k(
    const float* __restrict__ QKV, const float* __restrict__ Vt,
    float* __restrict__ O)
{
    extern __shared__ float sm[];
    float* Qs  = sm;                 // 128*68
    float* Ks  = Qs  + 128 * 68;     // 64*68
    float* Vts = Ks  +  64 * 68;     // 64*68
    float* Ps  = Vts +  64 * 68;     // 128*68

    const int t = threadIdx.x, w = t >> 5, lane = t & 31;
    const int gp = lane >> 2, qd = lane & 3;
    const int q0 = blockIdx.x * 128;
    const int h = blockIdx.y, b = blockIdx.z;

    const float* qb  = QKV + ((size_t)b * NQ) * 1536 + h * 64;
    const float* kb  = qb + 512;
    const float* vtb = Vt + ((size_t)(b * 8 + h)) * 64 * NQ;

    const uint32_t aQ = smem_u32(Qs), aK = smem_u32(Ks), aV = smem_u32(Vts);

    // load + scale Q tile (128 x 64)
    #pragma unroll
    for (int i = 0; i < 8; i++) {
        int idx = t + i * 256, r = idx >> 4, c4 = (idx & 15) * 4;
        cp16(aQ + (r * 68 + c4) * 4, &qb[(size_t)(q0 + r) * 1536 + c4], true);
    }
    CP_COMMIT(); CP_WAIT(0);
    __syncthreads();
    #pragma unroll
    for (int i = 0; i < 8; i++) {
        int idx = t + i * 256, r = idx >> 4, c4 = (idx & 15) * 4;
        float4* p = (float4*)&Qs[r * 68 + c4];
        float4 v = *p;
        v.x *= 0.125f; v.y *= 0.125f; v.z *= 0.125f; v.w *= 0.125f;
        *p = v;
    }
    __syncthreads();

    const int r0l = w * 16 + gp, r1l = r0l + 8;

    float o[8][4];
    #pragma unroll
    for (int nt = 0; nt < 8; nt++)
        #pragma unroll
        for (int c = 0; c < 4; c++) o[nt][c] = 0.f;
    float m0 = -1e30f, m1 = -1e30f, l0 = 0.f, l1 = 0.f;

    for (int kt = 0; kt < NQ / 64; kt++) {
        const int k0 = kt * 64;
        #pragma unroll
        for (int i = 0; i < 4; i++) {
            int idx = t + i * 256, r = idx >> 4, c4 = (idx & 15) * 4;
            cp16(aK + (r * 68 + c4) * 4, &kb[(size_t)(k0 + r) * 1536 + c4], true);
        }
        #pragma unroll
        for (int i = 0; i < 4; i++) {
            int idx = t + i * 256, d = idx >> 4, c4 = (idx & 15) * 4;
            cp16(aV + (d * 68 + c4) * 4, &vtb[(size_t)d * NQ + k0 + c4], true);
        }
        CP_COMMIT(); CP_WAIT(0);
        __syncthreads();

        // S = Qs @ Ks^T
        float s[8][4];
        #pragma unroll
        for (int nt = 0; nt < 8; nt++)
            #pragma unroll
            for (int c = 0; c < 4; c++) s[nt][c] = 0.f;
        #pragma unroll
        for (int ks = 0; ks < 8; ks++) {
            const int kc = ks * 8 + qd;
            uint32_t af[4];
            af[0] = U32(Qs[r0l * 68 + kc    ]);
            af[1] = U32(Qs[r1l * 68 + kc    ]);
            af[2] = U32(Qs[r0l * 68 + kc + 4]);
            af[3] = U32(Qs[r1l * 68 + kc + 4]);
            #pragma unroll
            for (int nt = 0; nt < 8; nt++) {
                uint32_t bf[2];
                const int n = nt * 8 + gp;
                bf[0] = U32(Ks[n * 68 + kc    ]);
                bf[1] = U32(Ks[n * 68 + kc + 4]);
                mma_t(s[nt], af, bf);
            }
        }

        // online softmax
        float tm0 = -1e30f, tm1 = -1e30f;
        #pragma unroll
        for (int nt = 0; nt < 8; nt++) {
            tm0 = fmaxf(tm0, fmaxf(s[nt][0], s[nt][1]));
            tm1 = fmaxf(tm1, fmaxf(s[nt][2], s[nt][3]));
        }
        tm0 = fmaxf(tm0, __shfl_xor_sync(~0u, tm0, 1));
        tm0 = fmaxf(tm0, __shfl_xor_sync(~0u, tm0, 2));
        tm1 = fmaxf(tm1, __shfl_xor_sync(~0u, tm1, 1));
        tm1 = fmaxf(tm1, __shfl_xor_sync(~0u, tm1, 2));
        const float mn0 = fmaxf(m0, tm0), mn1 = fmaxf(m1, tm1);
        const float al0 = __expf(m0 - mn0), al1 = __expf(m1 - mn1);
        float sum0 = 0.f, sum1 = 0.f;
        #pragma unroll
        for (int nt = 0; nt < 8; nt++) {
            s[nt][0] = __expf(s[nt][0] - mn0);
            s[nt][1] = __expf(s[nt][1] - mn0);
            s[nt][2] = __expf(s[nt][2] - mn1);
            s[nt][3] = __expf(s[nt][3] - mn1);
            sum0 += s[nt][0] + s[nt][1];
            sum1 += s[nt][2] + s[nt][3];
        }
        sum0 += __shfl_xor_sync(~0u, sum0, 1);
        sum0 += __shfl_xor_sync(~0u, sum0, 2);
        sum1 += __shfl_xor_sync(~0u, sum1, 1);
        sum1 += __shfl_xor_sync(~0u, sum1, 2);
        l0 = l0 * al0 + sum0;  m0 = mn0;
        l1 = l1 * al1 + sum1;  m1 = mn1;
        #pragma unroll
        for (int nt = 0; nt < 8; nt++) {
            o[nt][0] *= al0; o[nt][1] *= al0;
            o[nt][2] *= al1; o[nt][3] *= al1;
        }
        // store P to smem
        #pragma unroll
        for (int nt = 0; nt < 8; nt++) {
            *(float2*)&Ps[r0l * 68 + nt * 8 + 2 * qd] = make_float2(s[nt][0], s[nt][1]);
            *(float2*)&Ps[r1l * 68 + nt * 8 + 2 * qd] = make_float2(s[nt][2], s[nt][3]);
        }
        __syncthreads();

        // O += P @ Vt^T
        #pragma unroll
        for (int ks = 0; ks < 8; ks++) {
            const int kc = ks * 8 + qd;
            uint32_t af[4];
            af[0] = U32(Ps[r0l * 68 + kc    ]);
            af[1] = U32(Ps[r1l * 68 + kc    ]);
            af[2] = U32(Ps[r0l * 68 + kc + 4]);
            af[3] = U32(Ps[r1l * 68 + kc + 4]);
            #pragma unroll
            for (int nt = 0; nt < 8; nt++) {
                uint32_t bf[2];
                const int n = nt * 8 + gp;
                bf[0] = U32(Vts[n * 68 + kc    ]);
                bf[1] = U32(Vts[n * 68 + kc + 4]);
                mma_t(o[nt], af, bf);
            }
        }
        __syncthreads();
    }

    const float i0 = 1.f / l0, i1 = 1.f / l1;
    const size_t gr0 = (size_t)(b * NQ + q0 + r0l);
    const size_t gr1 = gr0 + 8;
    #pragma unroll
    for (int nt = 0; nt < 8; nt++) {
        const int col = h * 64 + nt * 8 + 2 * qd;
        *(float2*)&O[gr0 * 512 + col] = make_float2(o[nt][0] * i0, o[nt][1] * i0);
        *(float2*)&O[gr1 * 512 + col] = make_float2(o[nt][2] * i1, o[nt][3] * i1);
    }
}

// ---------------- batched weight transpose (+rna round) ----------------------
struct TrJobs {
    const float* src[12];
    float*       dst[12];
    int K[12], N[12], tiles[12];
};
__global__ void trall_k(TrJobs J)
{
    __shared__ float tl[32][33];
    int bid = blockIdx.x, j = 0;
    #pragma unroll
    for (int i = 0; i < 12; i++) {
        if (bid >= J.tiles[j]) { bid -= J.tiles[j]; j++; }
        else break;
    }
    const int kt = bid % (J.K[j] / 32), nt = bid / (J.K[j] / 32);
    const int k0 = kt * 32, n0 = nt * 32;
    const float* W = J.src[j];
    float* Wt = J.dst[j];
    const int K = J.K[j], N = J.N[j];
    int tx = threadIdx.x, ty = threadIdx.y;
    #pragma unroll
    for (int i = 0; i < 4; i++) {
        float v = W[(size_t)(k0 + ty + i * 8) * N + n0 + tx];
        tl[ty + i * 8][tx] = __uint_as_float(f2tf(v));
    }
    __syncthreads();
    #pragma unroll
    for (int i = 0; i < 4; i++)
        Wt[(size_t)(n0 + ty + i * 8) * K + k0 + tx] = tl[tx][ty + i * 8];
}

// ---------------- per-head V transpose: qkv v-section -> Vt[bh][64][NQ] ------
__global__ void vtr_k(const float* __restrict__ QKV, float* __restrict__ Vt)
{
    __shared__ float tl[32][33];
    int j0 = blockIdx.x * 32, d0 = blockIdx.y * 32, z = blockIdx.z;
    int b = z >> 3, h = z & 7;
    int tx = threadIdx.x, ty = threadIdx.y;
    #pragma unroll
    for (int i = 0; i < 4; i++)
        tl[ty + i * 8][tx] =
            QKV[((size_t)b * NQ + j0 + ty + i * 8) * 1536 + 1024 + h * DHEAD_ + d0 + tx];
    __syncthreads();
    #pragma unroll
    for (int i = 0; i < 4; i++)
        Vt[(size_t)z * DHEAD_ * NQ + (size_t)(d0 + ty + i * 8) * NQ + j0 + tx] = tl[tx][ty + i * 8];
}

// ---------------- GroupNorm stats -------------------------------------------
__global__ void gn_stats_k(const float* __restrict__ x, float* __restrict__ st)
{
    int bg = blockIdx.x, b = bg >> 5, g = bg & 31;
    const float* base = x + ((size_t)b * CC + (size_t)g * 16) * NQ;
    float s = 0.f, s2 = 0.f;
    for (int i = threadIdx.x; i < 16 * NQ; i += 256) {
        float v = base[i]; s += v; s2 += v * v;
    }
    for (int o = 16; o > 0; o >>= 1) {
        s  += __shfl_down_sync(~0u, s,  o);
        s2 += __shfl_down_sync(~0u, s2, o);
    }
    __shared__ float sh1[8], sh2[8];
    int w = threadIdx.x >> 5, lane = threadIdx.x & 31;
    if (lane == 0) { sh1[w] = s; sh2[w] = s2; }
    __syncthreads();
    if (threadIdx.x == 0) {
        float S = 0.f, S2 = 0.f;
        for (int i = 0; i < 8; i++) { S += sh1[i]; S2 += sh2[i]; }
        float mean = S / (16.f * NQ);
        float var  = S2 / (16.f * NQ) - mean * mean;
        st[bg * 2]     = mean;
        st[bg * 2 + 1] = rsqrtf(var + 1e-6f);
    }
}

// --------- GroupNorm apply + NCHW -> [b,n,c] transpose -----------------------
__global__ void gn_apply_t_k(const float* __restrict__ x, const float* __restrict__ st,
                             const float* __restrict__ gg, const float* __restrict__ gb,
                             float* __restrict__ o)
{
    __shared__ float tile[32][33];
    int n0 = blockIdx.x * 32, c0 = blockIdx.y * 32, b = blockIdx.z;
    int tx = threadIdx.x, ty = threadIdx.y;
    #pragma unroll
    for (int i = 0; i < 4; i++) {
        int c = c0 + ty + i * 8;
        int g = c >> 4;
        float mean = st[(b * 32 + g) * 2], rstd = st[(b * 32 + g) * 2 + 1];
        float v = x[((size_t)b * CC + c) * NQ + n0 + tx];
        tile[ty + i * 8][tx] = (v - mean) * rstd * gg[c] + gb[c];
    }
    __syncthreads();
    #pragma unroll
    for (int i = 0; i < 4; i++) {
        int n = n0 + ty + i * 8;
        o[((size_t)b * NQ + n) * INNER_ + c0 + tx] = tile[tx][ty + i * 8];
    }
}

// --------- final: [b,n,c] -> NCHW + residual ---------------------------------
__global__ void out_add_k(const float* __restrict__ yb, const float* __restrict__ x,
                          float* __restrict__ o)
{
    __shared__ float tile[32][33];
    int n0 = blockIdx.x * 32, c0 = blockIdx.y * 32, b = blockIdx.z;
    int tx = threadIdx.x, ty = threadIdx.y;
    #pragma unroll
    for (int i = 0; i < 4; i++) {
        int n = n0 + ty + i * 8;
        tile[ty + i * 8][tx] = yb[((size_t)b * NQ + n) * INNER_ + c0 + tx];
    }
    __syncthreads();
    #pragma unroll
    for (int i = 0; i < 4; i++) {
        int c = c0 + ty + i * 8;
        size_t idx = ((size_t)b * CC + c) * NQ + n0 + tx;
        o[idx] = tile[tx][ty + i * 8] + x[idx];
    }
}

// ---------------- LayerNorm over 512 -----------------------------------------
__global__ void ln_k(const float* __restrict__ X, const float* __restrict__ g,
                     const float* __restrict__ bb, float* __restrict__ O)
{
    int row = blockIdx.x;
    int t = threadIdx.x;
    const float4 v = ((const float4*)(X + (size_t)row * INNER_))[t];
    float s  = v.x + v.y + v.z + v.w;
    float s2 = v.x*v.x + v.y*v.y + v.z*v.z + v.w*v.w;
    for (int o = 16; o > 0; o >>= 1) {
        s  += __shfl_down_sync(~0u, s,  o);
        s2 += __shfl_down_sync(~0u, s2, o);
    }
    __shared__ float sh1[4], sh2[4];
    int w = t >> 5, lane = t & 31;
    if (lane == 0) { sh1[w] = s; sh2[w] = s2; }
    __syncthreads();
    if (t == 0) {
        float S = sh1[0]+sh1[1]+sh1[2]+sh1[3];
        float S2 = sh2[0]+sh2[1]+sh2[2]+sh2[3];
        float mean = S / 512.f;
        float var  = S2 / 512.f - mean * mean;
        sh1[0] = mean; sh2[0] = rsqrtf(var + 1e-5f);
    }
    __syncthreads();
    float mean = sh1[0], rstd = sh2[0];
    float4 g4 = ((const float4*)g)[t];
    float4 b4 = ((const float4*)bb)[t];
    float4 o;
    o.x = (v.x-mean)*rstd*g4.x + b4.x;
    o.y = (v.y-mean)*rstd*g4.y + b4.y;
    o.z = (v.z-mean)*rstd*g4.z + b4.z;
    o.w = (v.w-mean)*rstd*g4.w + b4.w;
    ((float4*)(O + (size_t)row * INNER_))[t] = o;
}

// ---------------- fp32 flash attention (cross-attn, 77 keys) -----------------
__global__ void __launch_bounds__(256) attn_k(
    const float* __restrict__ Q, const float* __restrict__ Kb,
    const float* __restrict__ Vb, float* __restrict__ O,
    int n_q, int n_kv, int ldq, int ldkv)
{
    __shared__ float Qs[64][68];
    __shared__ float Ks[32][68];
    __shared__ float Vs[32][68];
    __shared__ float Sx[64][33];
    __shared__ float mrow[64], lrow[64], arow[64];

    const int t  = threadIdx.x;
    const int h  = blockIdx.y, b = blockIdx.z;
    const int q0 = blockIdx.x * 64;
    const float* qb = Q  + ((size_t)b * n_q ) * ldq  + h * DHEAD_;
    const float* kb = Kb + ((size_t)b * n_kv) * ldkv + h * DHEAD_;
    const float* vb = Vb + ((size_t)b * n_kv) * ldkv + h * DHEAD_;

    #pragma unroll
    for (int j = 0; j < 4; j++) {
        int idx4 = t + j * 256;
        int r = idx4 >> 4, c4 = (idx4 & 15) * 4;
        float4 v = *(const float4*)&qb[(size_t)(q0 + r) * ldq + c4];
        Qs[r][c4+0]=v.x; Qs[r][c4+1]=v.y; Qs[r][c4+2]=v.z; Qs[r][c4+3]=v.w;
    }
    if (t < 64) { mrow[t] = -1e30f; lrow[t] = 0.f; }

    float acc[16];
    #pragma unroll
    for (int i = 0; i < 16; i++) acc[i] = 0.f;
    const int r  = t >> 2;
    const int jq = t & 3;

    const int ntiles = (n_kv + 31) / 32;
    for (int kt = 0; kt < ntiles; kt++) {
        const int j0 = kt * 32;
        #pragma unroll
        for (int j = 0; j < 2; j++) {
            int idx4 = t + j * 256;
            int jr = idx4 >> 4, c4 = (idx4 & 15) * 4;
            int krow = j0 + jr;
            float4 kv = make_float4(0.f,0.f,0.f,0.f);
            float4 vv = make_float4(0.f,0.f,0.f,0.f);
            if (krow < n_kv) {
                kv = *(const float4*)&kb[(size_t)krow * ldkv + c4];
                vv = *(const float4*)&vb[(size_t)krow * ldkv + c4];
            }
            Ks[jr][c4+0]=kv.x; Ks[jr][c4+1]=kv.y; Ks[jr][c4+2]=kv.z; Ks[jr][c4+3]=kv.w;
            Vs[jr][c4+0]=vv.x; Vs[jr][c4+1]=vv.y; Vs[jr][c4+2]=vv.z; Vs[jr][c4+3]=vv.w;
        }
        __syncthreads();
        #pragma unroll
        for (int jj = 0; jj < 8; jj++) {
            int j = jq + 4*jj;
            float s = 0.f;
            #pragma unroll
            for (int d = 0; d < 64; d++) s += Qs[r][d] * Ks[j][d];
            Sx[r][j] = (j0 + j < n_kv) ? s * 0.125f : -1e30f;
        }
        __syncthreads();
        if (t < 64) {
            float m_old = mrow[t];
            float mnew = m_old;
            #pragma unroll 8
            for (int j = 0; j < 32; j++) mnew = fmaxf(mnew, Sx[t][j]);
            float alpha = __expf(m_old - mnew);
            float psum = 0.f;
            #pragma unroll 8
            for (int j = 0; j < 32; j++) {
                float p = __expf(Sx[t][j] - mnew);
                Sx[t][j] = p; psum += p;
            }
            mrow[t] = mnew;
            lrow[t] = lrow[t]*alpha + psum;
            arow[t] = alpha;
        }
        __syncthreads();
        float alpha = arow[r];
        #pragma unroll
        for (int i = 0; i < 16; i++) acc[i] *= alpha;
        #pragma unroll 4
        for (int j = 0; j < 32; j++) {
            float p = Sx[r][j];
            #pragma unroll
            for (int i = 0; i < 16; i++)
                acc[i] += p * Vs[j][jq + 4*i];
        }
        __syncthreads();
    }
    const float inv = 1.f / lrow[r];
    float* orow = O + ((size_t)(b * n_q + q0 + r)) * INNER_ + h * DHEAD_ + jq;
    #pragma unroll
    for (int i = 0; i < 16; i++) orow[4*i] = acc[i] * inv;
}

// ---------------- GEGLU -------------------------------------------------------
__global__ void geglu_k(const float* __restrict__ ff, float* __restrict__ gl)
{
    int idx = blockIdx.x * 256 + threadIdx.x;
    int row = idx / FFI, col = idx - row * FFI;
    float a = ff[(size_t)row * 4096 + col];
    float g = ff[(size_t)row * 4096 + 2048 + col];
    gl[idx] = a * (0.5f * g * (1.f + erff(g * 0.70710678118654752f)));
}

// ---------------- launch -------------------------------------------------------
extern "C" void kernel_launch(void* const* d_in, const int* in_sizes, int n_in,
                              void* d_out, int out_size)
{
    const float* x    = (const float*)d_in[0];
    const float* ctx  = (const float*)d_in[1];
    const float* gng  = (const float*)d_in[2];
    const float* gnb  = (const float*)d_in[3];
    const float* w_in = (const float*)d_in[4];
    const float* b_in = (const float*)d_in[5];
    const float* ln1g = (const float*)d_in[6];
    const float* ln1b = (const float*)d_in[7];
    const float* wq1  = (const float*)d_in[8];
    const float* wk1  = (const float*)d_in[9];
    const float* wv1  = (const float*)d_in[10];
    const float* wo1  = (const float*)d_in[11];
    const float* bo1  = (const float*)d_in[12];
    const float* ln2g = (const float*)d_in[13];
    const float* ln2b = (const float*)d_in[14];
    const float* wq2  = (const float*)d_in[15];
    const float* wk2  = (const float*)d_in[16];
    const float* wv2  = (const float*)d_in[17];
    const float* wo2  = (const float*)d_in[18];
    const float* bo2  = (const float*)d_in[19];
    const float* ln3g = (const float*)d_in[20];
    const float* ln3b = (const float*)d_in[21];
    const float* wff1 = (const float*)d_in[22];
    const float* bff1 = (const float*)d_in[23];
    const float* wff2 = (const float*)d_in[24];
    const float* bff2 = (const float*)d_in[25];
    const float* wout = (const float*)d_in[26];
    const float* bout = (const float*)d_in[27];
    float* out = (float*)d_out;

    float *hn,*t_,*q,*at,*y,*qkv,*kvc,*ff,*gl,*st,*vt;
    float *wt_in,*wqkv,*wto1,*wtq2,*wtkv2,*wto2,*wtff1,*wtff2,*wtout;
    cudaGetSymbolAddress((void**)&hn,  g_hn);
    cudaGetSymbolAddress((void**)&t_,  g_t);
    cudaGetSymbolAddress((void**)&q,   g_q);
    cudaGetSymbolAddress((void**)&at,  g_at);
    cudaGetSymbolAddress((void**)&y,   g_y);
    cudaGetSymbolAddress((void**)&qkv, g_qkv);
    cudaGetSymbolAddress((void**)&kvc, g_kvc);
    cudaGetSymbolAddress((void**)&ff,  g_ff);
    cudaGetSymbolAddress((void**)&gl,  g_gl);
    cudaGetSymbolAddress((void**)&st,  g_stat);
    cudaGetSymbolAddress((void**)&vt,  g_vt);
    cudaGetSymbolAddress((void**)&wt_in, g_wt_in);
    cudaGetSymbolAddress((void**)&wqkv,  g_wqkv);
    cudaGetSymbolAddress((void**)&wto1,  g_wto1);
    cudaGetSymbolAddress((void**)&wtq2,  g_wtq2);
    cudaGetSymbolAddress((void**)&wtkv2, g_wtkv2);
    cudaGetSymbolAddress((void**)&wto2,  g_wto2);
    cudaGetSymbolAddress((void**)&wtff1, g_wtff1);
    cudaGetSymbolAddress((void**)&wtff2, g_wtff2);
    cudaGetSymbolAddress((void**)&wtout, g_wtout);

    const int SM128 = 2 * (128 * 36 + 128 * 36) * 4;   // 73728
    const int SMFA  = 384 * 68 * 4;                    // 104448
    cudaFuncSetAttribute(tgemm_k<128>, cudaFuncAttributeMaxDynamicSharedMemorySize, SM128);
    cudaFuncSetAttribute(fattn_k, cudaFuncAttributeMaxDynamicSharedMemorySize, SMFA);

    const dim3 tb(32, 8);

    // batched weight transposes (+tf32 rna pre-rounding)
    TrJobs J;
    J.src[0]=w_in;  J.dst[0]=wt_in;            J.K[0]=512;  J.N[0]=512;
    J.src[1]=wq1;   J.dst[1]=wqkv;             J.K[1]=512;  J.N[1]=512;
    J.src[2]=wk1;   J.dst[2]=wqkv+512*512;     J.K[2]=512;  J.N[2]=512;
    J.src[3]=wv1;   J.dst[3]=wqkv+1024*512;    J.K[3]=512;  J.N[3]=512;
    J.src[4]=wo1;   J.dst[4]=wto1;             J.K[4]=512;  J.N[4]=512;
    J.src[5]=wq2;   J.dst[5]=wtq2;             J.K[5]=512;  J.N[5]=512;
    J.src[6]=wk2;   J.dst[6]=wtkv2;            J.K[6]=768;  J.N[6]=512;
    J.src[7]=wv2;   J.dst[7]=wtkv2+512*768;    J.K[7]=768;  J.N[7]=512;
    J.src[8]=wo2;   J.dst[8]=wto2;             J.K[8]=512;  J.N[8]=512;
    J.src[9]=wff1;  J.dst[9]=wtff1;            J.K[9]=512;  J.N[9]=4096;
    J.src[10]=wff2; J.dst[10]=wtff2;           J.K[10]=2048;J.N[10]=512;
    J.src[11]=wout; J.dst[11]=wtout;           J.K[11]=512; J.N[11]=512;
    int tot = 0;
    for (int i = 0; i < 12; i++) { J.tiles[i] = (J.K[i]/32)*(J.N[i]/32); tot += J.tiles[i]; }
    trall_k<<<tot, tb>>>(J);

    // GroupNorm + proj_in
    gn_stats_k  <<<BB*32, 256>>>(x, st);
    gn_apply_t_k<<<dim3(72, 16, 2), tb>>>(x, st, gng, gnb, hn);
    tgemm_k<128><<<dim3(4, 36), 256, SM128>>>(hn, wt_in, b_in, nullptr, t_,
        MTOK, 512, 512, 512, 512);

    // self-attention
    ln_k<<<MTOK, 128>>>(t_, ln1g, ln1b, hn);
    tgemm_k<128><<<dim3(12, 36), 256, SM128>>>(hn, wqkv, nullptr, nullptr, qkv,
        MTOK, 512, 512, 512, 1536);
    vtr_k<<<dim3(72, 2, 16), tb>>>(qkv, vt);
    fattn_k<<<dim3(18, 8, 2), 256, SMFA>>>(qkv, vt, at);
    tgemm_k<128><<<dim3(4, 36), 256, SM128>>>(at, wto1, bo1, t_, t_,
        MTOK, 512, 512, 512, 512);

    // cross-attention
    ln_k<<<MTOK, 128>>>(t_, ln2g, ln2b, hn);
    tgemm_k<128><<<dim3(4, 36), 256, SM128>>>(hn, wtq2, nullptr, nullptr, q,
        MTOK, 512, 512, 512, 512);
    tgemm_k<128><<<dim3(8, 2), 256, SM128>>>(ctx, wtkv2, nullptr, nullptr, kvc,
        BB*CTX, 768, 768, 768, 1024);
    attn_k<<<dim3(36, 8, 2), 256>>>(q, kvc, kvc + 512, at, NQ, CTX, 512, 1024);
    tgemm_k<128><<<dim3(4, 36), 256, SM128>>>(at, wto2, bo2, t_, t_,
        MTOK, 512, 512, 512, 512);

    // feed-forward (GEGLU)
    ln_k<<<MTOK, 128>>>(t_, ln3g, ln3b, hn);
    tgemm_k<128><<<dim3(32, 36), 256, SM128>>>(hn, wtff1, bff1, nullptr, ff,
        MTOK, 512, 512, 512, 4096);
    geglu_k<<<(MTOK*FFI)/256, 256>>>(ff, gl);
    tgemm_k<128><<<dim3(4, 36), 256, SM128>>>(gl, wtff2, bff2, t_, t_,
        MTOK, 2048, 2048, 2048, 512);

    // proj_out + residual
    tgemm_k<128><<<dim3(4, 36), 256, SM128>>>(t_, wtout, bout, nullptr, y,
        MTOK, 512, 512, 512, 512);
    out_add_k<<<dim3(72, 16, 2), tb>>>(y, x, out);
}